// round 10
// baseline (speedup 1.0000x reference)
#include <cuda_runtime.h>
#include <math.h>
#include <stdint.h>

#define CHUNKT   128
#define BM       128
#define BN       128     // 112 cols via mma + 16 cols via FFMA warps
#define NMMA     112
#define BK       32
#define KSTR     36      // smem row stride in floats: 144B, 16B-aligned, conflict-free
#define MATB     (128 * KSTR * 4)          // bytes per matrix per stage (18432)
#define STAGEB   (2 * MATB)                // bytes per stage (A + B) = 36864
#define NSTAGE   3
#define NTHREADS 384

// W^T as tf32 bit patterns (valid fp32 values), [H][D] K-major.
__device__ uint32_t g_WT[1024 * 1024];

// ---------------------------------------------------------------------------
// helpers
// ---------------------------------------------------------------------------
__device__ __forceinline__ uint32_t cvta_shared(const void* p) {
    uint32_t a;
    asm("{ .reg .u64 t; cvta.to.shared.u64 t, %1; cvt.u32.u64 %0, t; }" : "=r"(a) : "l"(p));
    return a;
}
__device__ __forceinline__ void cp_async16(uint32_t dst, const void* src) {
    asm volatile("cp.async.cg.shared.global [%0], [%1], 16;" :: "r"(dst), "l"(src));
}
__device__ __forceinline__ uint32_t f2tf32(float x) {
    uint32_t r;
    asm("cvt.rna.tf32.f32 %0, %1;" : "=r"(r) : "f"(x));
    return r;
}
__device__ __forceinline__ void mma_tf32(float c[4], uint32_t a0, uint32_t a1,
                                         uint32_t a2, uint32_t a3,
                                         uint32_t b0, uint32_t b1) {
    asm volatile(
        "mma.sync.aligned.m16n8k8.row.col.f32.tf32.tf32.f32 "
        "{%0,%1,%2,%3}, {%4,%5,%6,%7}, {%8,%9}, {%0,%1,%2,%3};"
        : "+f"(c[0]), "+f"(c[1]), "+f"(c[2]), "+f"(c[3])
        : "r"(a0), "r"(a1), "r"(a2), "r"(a3), "r"(b0), "r"(b1));
}

// ---------------------------------------------------------------------------
// Kernel 1: W[D,H] -> g_WT[H,D] with fp32 -> tf32(rna) conversion fused.
// ---------------------------------------------------------------------------
__global__ void transpose_kernel(const float* __restrict__ W, int D, int H) {
    __shared__ float tile[32][33];
    int h0 = blockIdx.x * 32, d0 = blockIdx.y * 32;
    int tx = threadIdx.x, ty = threadIdx.y;   // 32 x 8
    #pragma unroll
    for (int i = 0; i < 32; i += 8)
        tile[ty + i][tx] = W[(size_t)(d0 + ty + i) * H + h0 + tx];
    __syncthreads();
    #pragma unroll
    for (int i = 0; i < 32; i += 8)
        g_WT[(size_t)(h0 + ty + i) * D + d0 + tx] = f2tf32(tile[tx][ty + i]);
}

// ---------------------------------------------------------------------------
// Kernel 2: hybrid tensor+FMA GEMM. One CTA = 128(M = one chunk) x 128(N).
// Warps 0-7: mma tf32 over cols 0..111 (4m x 2n, warp tile 32x56).
// Warps 8-11 (one per SMSP): FFMA over cols 112..127 from the same stages.
// cp.async 3-stage pipeline, BK=32. Selection computed inline (no select
// kernel). Epilogue fuses (+bias +PE(t,h)) * sqrt(128). Dead slots zero-fill.
// ---------------------------------------------------------------------------
__global__ void __launch_bounds__(NTHREADS, 2)
chunk_gemm_mma(const float* __restrict__ data,
               const float* __restrict__ bias,
               const int* __restrict__ chunk_idx,
               float* __restrict__ out,
               int D, int H, int T, int sample) {
    extern __shared__ __align__(16) char smem[];
    __shared__ float s_div[BN / 2];
    __shared__ float s_bias[BN];

    const int ntile = blockIdx.x;
    const int slot  = blockIdx.y;
    const int b     = blockIdx.z;
    const int n0    = ntile * BN;
    const int Smax  = sample * CHUNKT;
    const int tid   = threadIdx.x;
    const int wid   = tid >> 5;
    const int lane  = tid & 31;

    float* outp = out + ((size_t)b * Smax + (size_t)slot * CHUNKT) * H + n0;

    // Inline selection: sorted-unique chunk list == set bits of the mask.
    unsigned long long mask = 0ull;
    #pragma unroll
    for (int i = 0; i < 16; ++i) mask |= (1ull << chunk_idx[b * sample + i]);
    const int nsel = __popcll(mask);

    if (slot >= nsel) {                      // zero-fill 128 x 128 tile
        float4 z = make_float4(0.f, 0.f, 0.f, 0.f);
        for (int idx = tid; idx < 128 * 32; idx += NTHREADS) {
            int r = idx >> 5, c4 = (idx & 31) * 4;
            *reinterpret_cast<float4*>(outp + (size_t)r * H + c4) = z;
        }
        return;
    }

    int chunk = 0;
    {   // position of (slot+1)-th set bit
        int s = slot;
        #pragma unroll 8
        for (int c = 0; c < 64; ++c) {
            if ((mask >> c) & 1ull) { if (s == 0) { chunk = c; break; } --s; }
        }
    }

    const float*    Agm = data + (size_t)b * T * D + (size_t)chunk * CHUNKT * D;
    const uint32_t* Bgm = g_WT + (size_t)n0 * D;

    if (tid < BN / 2)
        s_div[tid] = __expf((float)(2 * ((n0 >> 1) + tid)) * (-9.210340371976184f / (float)H));
    if (tid < BN) s_bias[tid] = bias[n0 + tid];

    const uint32_t sbase = cvta_shared(smem);

    // cp.async map (first 256 threads): 4+4 x 16B copies per stage.
    const int cp_row = (tid & 255) >> 3;
    const int cp_kp  = tid & 7;
    const bool loader = (tid < 256);

    auto load_stage = [&](int kc, int st) {
        if (loader) {
            const int k0 = kc * BK;
            const uint32_t abase = sbase + st * STAGEB;
            const uint32_t bbase = abase + MATB;
            #pragma unroll
            for (int i = 0; i < 4; ++i) {
                int r = cp_row + i * 32;
                cp_async16(abase + r * (KSTR * 4) + cp_kp * 16,
                           Agm + (size_t)r * D + k0 + cp_kp * 4);
            }
            #pragma unroll
            for (int i = 0; i < 4; ++i) {
                int r = cp_row + i * 32;
                cp_async16(bbase + r * (KSTR * 4) + cp_kp * 16,
                           Bgm + (size_t)r * D + k0 + cp_kp * 4);
            }
        }
        asm volatile("cp.async.commit_group;" ::: "memory");
    };

    const int NCH = D / BK;                  // 32
    load_stage(0, 0);
    load_stage(1, 1);

    if (wid < 8) {
        // ---------------- mma warps: cols 0..111 ----------------
        const int wm = wid >> 1;             // 0..3 -> 32-row tile
        const int wn = wid & 1;              // 0..1 -> 56-col tile
        float acc[2][7][4];
        #pragma unroll
        for (int mt = 0; mt < 2; ++mt)
            #pragma unroll
            for (int nt = 0; nt < 7; ++nt)
                #pragma unroll
                for (int q = 0; q < 4; ++q) acc[mt][nt][q] = 0.f;

        for (int c = 0; c < NCH; ++c) {
            asm volatile("cp.async.wait_group 1;" ::: "memory");
            __syncthreads();
            if (c + 2 < NCH) load_stage(c + 2, (c + 2) % NSTAGE);
            else             asm volatile("cp.async.commit_group;" ::: "memory");

            const float*    Ab = reinterpret_cast<const float*>(smem + (c % NSTAGE) * STAGEB);
            const uint32_t* Bb = reinterpret_cast<const uint32_t*>(smem + (c % NSTAGE) * STAGEB + MATB);

            #pragma unroll
            for (int k8 = 0; k8 < 4; ++k8) {
                const int kk = k8 * 8 + (lane & 3);
                uint32_t af[2][4], bf[7][2];
                #pragma unroll
                for (int mt = 0; mt < 2; ++mt) {
                    const int mr = wm * 32 + mt * 16 + (lane >> 2);
                    af[mt][0] = f2tf32(Ab[(mr)     * KSTR + kk]);
                    af[mt][1] = f2tf32(Ab[(mr + 8) * KSTR + kk]);
                    af[mt][2] = f2tf32(Ab[(mr)     * KSTR + kk + 4]);
                    af[mt][3] = f2tf32(Ab[(mr + 8) * KSTR + kk + 4]);
                }
                #pragma unroll
                for (int nt = 0; nt < 7; ++nt) {
                    const int nr = wn * 56 + nt * 8 + (lane >> 2);
                    bf[nt][0] = Bb[nr * KSTR + kk];
                    bf[nt][1] = Bb[nr * KSTR + kk + 4];
                }
                #pragma unroll
                for (int mt = 0; mt < 2; ++mt)
                    #pragma unroll
                    for (int nt = 0; nt < 7; ++nt)
                        mma_tf32(acc[mt][nt], af[mt][0], af[mt][1], af[mt][2], af[mt][3],
                                 bf[nt][0], bf[nt][1]);
            }
        }

        // mma epilogue
        const float scale = 11.313708498984761f;   // sqrt(128)
        const int qrow = lane >> 2, qcol = (lane & 3) * 2;
        #pragma unroll
        for (int mt = 0; mt < 2; ++mt) {
            #pragma unroll
            for (int nt = 0; nt < 7; ++nt) {
                const int col = wn * 56 + nt * 8 + qcol;
                const float bs0 = s_bias[col], bs1 = s_bias[col + 1];
                const float dv  = s_div[col >> 1];
                #pragma unroll
                for (int h = 0; h < 2; ++h) {
                    const int row = wm * 32 + mt * 16 + h * 8 + qrow;
                    float s, cc;
                    __sincosf((float)(chunk * CHUNKT + row) * dv, &s, &cc);
                    float2 v;
                    v.x = (acc[mt][nt][h * 2 + 0] + bs0 + s)  * scale;
                    v.y = (acc[mt][nt][h * 2 + 1] + bs1 + cc) * scale;
                    *reinterpret_cast<float2*>(outp + (size_t)row * H + col) = v;
                }
            }
        }
    } else {
        // ---------------- FFMA warps: cols 112..127 ----------------
        const int wf  = wid - 8;             // 0..3 (one per SMSP)
        const int rr  = lane >> 2;           // 0..7 row group
        const int cc  = lane & 3;            // 0..3 col within warp's 4
        const int col = NMMA + wf * 4 + cc;  // 112..127
        float acc[16];
        #pragma unroll
        for (int j = 0; j < 16; ++j) acc[j] = 0.f;

        for (int c = 0; c < NCH; ++c) {
            asm volatile("cp.async.wait_group 1;" ::: "memory");
            __syncthreads();
            if (c + 2 < NCH) load_stage(c + 2, (c + 2) % NSTAGE);
            else             asm volatile("cp.async.commit_group;" ::: "memory");

            const float* Ab = reinterpret_cast<const float*>(smem + (c % NSTAGE) * STAGEB);
            const float* Bb = reinterpret_cast<const float*>(smem + (c % NSTAGE) * STAGEB + MATB);

            #pragma unroll
            for (int k4 = 0; k4 < 8; ++k4) {
                const float4 bv = *reinterpret_cast<const float4*>(&Bb[col * KSTR + k4 * 4]);
                #pragma unroll
                for (int j = 0; j < 16; ++j) {
                    const float4 av =
                        *reinterpret_cast<const float4*>(&Ab[(rr + 8 * j) * KSTR + k4 * 4]);
                    acc[j] = fmaf(av.x, bv.x, acc[j]);
                    acc[j] = fmaf(av.y, bv.y, acc[j]);
                    acc[j] = fmaf(av.z, bv.z, acc[j]);
                    acc[j] = fmaf(av.w, bv.w, acc[j]);
                }
            }
        }

        // ffma epilogue
        const float scale = 11.313708498984761f;
        const float bs = s_bias[col];
        const float dv = s_div[col >> 1];
        const bool  odd = (col & 1);
        #pragma unroll
        for (int j = 0; j < 16; ++j) {
            const int row = rr + 8 * j;
            float s, cosv;
            __sincosf((float)(chunk * CHUNKT + row) * dv, &s, &cosv);
            outp[(size_t)row * H + col] = (acc[j] + bs + (odd ? cosv : s)) * scale;
        }
    }
}

// ---------------------------------------------------------------------------
// Launcher. Inputs: state, data, W, b, chunk_idx. Output float32.
// ---------------------------------------------------------------------------
extern "C" void kernel_launch(void* const* d_in, const int* in_sizes, int n_in,
                              void* d_out, int out_size) {
    const float* data      = (const float*)d_in[1];
    const float* W         = (const float*)d_in[2];
    const float* bias      = (const float*)d_in[3];
    const int*   chunk_idx = (const int*)d_in[4];
    float*       out       = (float*)d_out;

    const int H = in_sizes[3];                // 1024
    const int D = in_sizes[2] / H;            // 1024
    const int B = in_sizes[0] / (64 * H);     // 8
    const int T = in_sizes[1] / (B * D);      // 8192
    const int sample = in_sizes[4] / B;       // 16

    transpose_kernel<<<dim3(H / 32, D / 32), dim3(32, 8)>>>(W, D, H);

    const int SMEM_BYTES = NSTAGE * STAGEB;   // 110592
    cudaFuncSetAttribute(chunk_gemm_mma,
                         cudaFuncAttributeMaxDynamicSharedMemorySize, SMEM_BYTES);
    dim3 grid(H / BN, sample, B);
    chunk_gemm_mma<<<grid, NTHREADS, SMEM_BYTES>>>(data, bias, chunk_idx, out,
                                                   D, H, T, sample);
}

// round 11
// speedup vs baseline: 2.3358x; 2.3358x over previous
#include <cuda_runtime.h>
#include <cuda_fp16.h>
#include <math.h>
#include <stdint.h>

#define CHUNKT   128
#define BM       128
#define BN       128
#define BK       32      // K elems per stage
#define KSTRA    40      // A smem row stride in floats (160B): LDS.64 conflict-free
#define KSTRB    40      // B smem row stride in halves (80B): LDS.32 conflict-free
#define AMATB    (128 * KSTRA * 4)         // 20480 B
#define BMATB    (128 * KSTRB * 2)         // 10240 B
#define STAGEB   (AMATB + BMATB)           // 30720 B
#define NSTAGE   3

// W^T as fp16, [H][D] K-major.
__device__ __half g_WT[1024 * 1024];

// ---------------------------------------------------------------------------
// helpers
// ---------------------------------------------------------------------------
__device__ __forceinline__ uint32_t cvta_shared(const void* p) {
    uint32_t a;
    asm("{ .reg .u64 t; cvta.to.shared.u64 t, %1; cvt.u32.u64 %0, t; }" : "=r"(a) : "l"(p));
    return a;
}
__device__ __forceinline__ void cp_async16(uint32_t dst, const void* src) {
    asm volatile("cp.async.cg.shared.global [%0], [%1], 16;" :: "r"(dst), "l"(src));
}
// pack {lo=x, hi=y} as f16x2
__device__ __forceinline__ uint32_t f2h2(float x, float y) {
    uint32_t r;
    asm("cvt.rn.f16x2.f32 %0, %1, %2;" : "=r"(r) : "f"(y), "f"(x));
    return r;
}
__device__ __forceinline__ void mma_f16(float c[4], uint32_t a0, uint32_t a1,
                                        uint32_t a2, uint32_t a3,
                                        uint32_t b0, uint32_t b1) {
    asm volatile(
        "mma.sync.aligned.m16n8k16.row.col.f32.f16.f16.f32 "
        "{%0,%1,%2,%3}, {%4,%5,%6,%7}, {%8,%9}, {%0,%1,%2,%3};"
        : "+f"(c[0]), "+f"(c[1]), "+f"(c[2]), "+f"(c[3])
        : "r"(a0), "r"(a1), "r"(a2), "r"(a3), "r"(b0), "r"(b1));
}

// ---------------------------------------------------------------------------
// Kernel 1: W[D,H] -> g_WT[H,D], fp32 -> fp16(rn) fused.
// ---------------------------------------------------------------------------
__global__ void transpose_kernel(const float* __restrict__ W, int D, int H) {
    __shared__ float tile[32][33];
    int h0 = blockIdx.x * 32, d0 = blockIdx.y * 32;
    int tx = threadIdx.x, ty = threadIdx.y;   // 32 x 8
    #pragma unroll
    for (int i = 0; i < 32; i += 8)
        tile[ty + i][tx] = W[(size_t)(d0 + ty + i) * H + h0 + tx];
    __syncthreads();
    #pragma unroll
    for (int i = 0; i < 32; i += 8)
        g_WT[(size_t)(h0 + ty + i) * D + d0 + tx] = __float2half_rn(tile[tx][ty + i]);
}

// ---------------------------------------------------------------------------
// Kernel 2: fp16 mma.sync GEMM (f32 accum). One CTA = 128(M=one chunk)x128(N).
// A fp32 in smem (cvt at fragment load), B fp16 in smem. cp.async 3-stage
// pipeline, BK=32, 8 warps (2m x 4n), warp tile 64x32, m16n8k16.
// Selection inlined. Epilogue fuses (+bias +PE(t,h)) * sqrt(128).
// ---------------------------------------------------------------------------
__global__ void __launch_bounds__(256, 2)
chunk_gemm_mma(const float* __restrict__ data,
               const float* __restrict__ bias,
               const int* __restrict__ chunk_idx,
               float* __restrict__ out,
               int D, int H, int T, int sample) {
    extern __shared__ __align__(16) char smem[];
    __shared__ float s_div[BN / 2];
    __shared__ float s_bias[BN];

    const int ntile = blockIdx.x;
    const int slot  = blockIdx.y;
    const int b     = blockIdx.z;
    const int n0    = ntile * BN;
    const int Smax  = sample * CHUNKT;
    const int tid   = threadIdx.x;
    const int wid   = tid >> 5;
    const int lane  = tid & 31;

    float* outp = out + ((size_t)b * Smax + (size_t)slot * CHUNKT) * H + n0;

    // Inline selection: sorted-unique chunks == ascending set bits of mask.
    unsigned long long mask = 0ull;
    #pragma unroll
    for (int i = 0; i < 16; ++i) mask |= (1ull << chunk_idx[b * sample + i]);
    const int nsel = __popcll(mask);

    if (slot >= nsel) {                      // zero-fill 128 x 128 tile
        float4 z = make_float4(0.f, 0.f, 0.f, 0.f);
        #pragma unroll
        for (int i = 0; i < 16; ++i) {
            int idx = i * 256 + tid;
            int r = idx >> 5, c4 = (idx & 31) * 4;
            *reinterpret_cast<float4*>(outp + (size_t)r * H + c4) = z;
        }
        return;
    }

    int chunk = 0;
    {   // position of (slot+1)-th set bit
        int s = slot;
        for (int c = 0; c < 64; ++c) {
            if ((mask >> c) & 1ull) { if (s == 0) { chunk = c; break; } --s; }
        }
    }

    const float*  Agm = data + (size_t)b * T * D + (size_t)chunk * CHUNKT * D;
    const __half* Bgm = g_WT + (size_t)n0 * D;

    if (tid < BN / 2)
        s_div[tid] = __expf((float)(2 * ((n0 >> 1) + tid)) * (-9.210340371976184f / (float)H));
    if (tid < BN) s_bias[tid] = bias[n0 + tid];

    const uint32_t sbase = cvta_shared(smem);

    // cp.async maps: A = 128 rows x 8 x16B (4/thread); B = 128 rows x 4 x16B (2/thread)
    const int a_row = tid >> 1;              // with +0/+... see below: use idx form
    (void)a_row;

    auto load_stage = [&](int kc, int st) {
        const int k0 = kc * BK;
        const uint32_t abase = sbase + st * STAGEB;
        const uint32_t bbase = abase + AMATB;
        #pragma unroll
        for (int i = 0; i < 4; ++i) {        // A: fp32
            int idx = i * 256 + tid;
            int r = idx >> 3, kp = idx & 7;
            cp_async16(abase + r * (KSTRA * 4) + kp * 16,
                       Agm + (size_t)r * D + k0 + kp * 4);
        }
        #pragma unroll
        for (int i = 0; i < 2; ++i) {        // B: fp16
            int idx = i * 256 + tid;
            int r = idx >> 2, kp = idx & 3;
            cp_async16(bbase + r * (KSTRB * 2) + kp * 16,
                       Bgm + (size_t)r * D + k0 + kp * 8);
        }
        asm volatile("cp.async.commit_group;" ::: "memory");
    };

    // Warp tiling: wm in {0,1} (64 rows), wn in {0..3} (32 cols)
    const int wm = wid & 1;
    const int wn = wid >> 1;

    float acc[4][4][4];
    #pragma unroll
    for (int mt = 0; mt < 4; ++mt)
        #pragma unroll
        for (int nt = 0; nt < 4; ++nt)
            #pragma unroll
            for (int q = 0; q < 4; ++q) acc[mt][nt][q] = 0.f;

    const int NCH = D / BK;                  // 32
    load_stage(0, 0);
    load_stage(1, 1);

    for (int c = 0; c < NCH; ++c) {
        asm volatile("cp.async.wait_group 1;" ::: "memory");
        __syncthreads();
        if (c + 2 < NCH) load_stage(c + 2, (c + 2) % NSTAGE);
        else             asm volatile("cp.async.commit_group;" ::: "memory");

        const float2*   Af2 = reinterpret_cast<const float2*>(smem + (c % NSTAGE) * STAGEB);
        const uint32_t* Bb  = reinterpret_cast<const uint32_t*>(smem + (c % NSTAGE) * STAGEB + AMATB);

        #pragma unroll
        for (int k16 = 0; k16 < 2; ++k16) {
            const int kb = k16 * 16 + (lane & 3) * 2;    // even half-index base
            uint32_t af[4][4], bf[4][2];
            #pragma unroll
            for (int mt = 0; mt < 4; ++mt) {
                const int mr = wm * 64 + mt * 16 + (lane >> 2);
                float2 p0 = Af2[(mr)     * 20 + (kb >> 1)];
                float2 p1 = Af2[(mr + 8) * 20 + (kb >> 1)];
                float2 p2 = Af2[(mr)     * 20 + ((kb + 8) >> 1)];
                float2 p3 = Af2[(mr + 8) * 20 + ((kb + 8) >> 1)];
                af[mt][0] = f2h2(p0.x, p0.y);
                af[mt][1] = f2h2(p1.x, p1.y);
                af[mt][2] = f2h2(p2.x, p2.y);
                af[mt][3] = f2h2(p3.x, p3.y);
            }
            #pragma unroll
            for (int nt = 0; nt < 4; ++nt) {
                const int nr = wn * 32 + nt * 8 + (lane >> 2);
                bf[nt][0] = Bb[nr * 20 + (kb >> 1)];
                bf[nt][1] = Bb[nr * 20 + ((kb + 8) >> 1)];
            }
            #pragma unroll
            for (int mt = 0; mt < 4; ++mt)
                #pragma unroll
                for (int nt = 0; nt < 4; ++nt)
                    mma_f16(acc[mt][nt], af[mt][0], af[mt][1], af[mt][2], af[mt][3],
                            bf[nt][0], bf[nt][1]);
        }
    }

    // Epilogue: (acc + bias + PE(t,h)) * sqrt(128)
    const float scale = 11.313708498984761f;   // sqrt(128)
    const int   qrow  = lane >> 2;             // 0..7
    const int   qcol  = (lane & 3) * 2;        // 0,2,4,6

    #pragma unroll
    for (int mt = 0; mt < 4; ++mt) {
        #pragma unroll
        for (int nt = 0; nt < 4; ++nt) {
            const int col = wn * 32 + nt * 8 + qcol;     // even local col
            const float bs0 = s_bias[col], bs1 = s_bias[col + 1];
            const float dv  = s_div[col >> 1];
            #pragma unroll
            for (int h = 0; h < 2; ++h) {                // row halves (+0, +8)
                const int row = wm * 64 + mt * 16 + h * 8 + qrow;
                float s, cc;
                __sincosf((float)(chunk * CHUNKT + row) * dv, &s, &cc);
                float2 v;
                v.x = (acc[mt][nt][h * 2 + 0] + bs0 + s)  * scale;
                v.y = (acc[mt][nt][h * 2 + 1] + bs1 + cc) * scale;
                *reinterpret_cast<float2*>(outp + (size_t)row * H + col) = v;
            }
        }
    }
}

// ---------------------------------------------------------------------------
// Launcher. Inputs: state, data, W, b, chunk_idx. Output float32.
// ---------------------------------------------------------------------------
extern "C" void kernel_launch(void* const* d_in, const int* in_sizes, int n_in,
                              void* d_out, int out_size) {
    const float* data      = (const float*)d_in[1];
    const float* W         = (const float*)d_in[2];
    const float* bias      = (const float*)d_in[3];
    const int*   chunk_idx = (const int*)d_in[4];
    float*       out       = (float*)d_out;

    const int H = in_sizes[3];                // 1024
    const int D = in_sizes[2] / H;            // 1024
    const int B = in_sizes[0] / (64 * H);     // 8
    const int T = in_sizes[1] / (B * D);      // 8192
    const int sample = in_sizes[4] / B;       // 16

    transpose_kernel<<<dim3(H / 32, D / 32), dim3(32, 8)>>>(W, D, H);

    const int SMEM_BYTES = NSTAGE * STAGEB;   // 92160
    cudaFuncSetAttribute(chunk_gemm_mma,
                         cudaFuncAttributeMaxDynamicSharedMemorySize, SMEM_BYTES);
    dim3 grid(H / BN, sample, B);
    chunk_gemm_mma<<<grid, 256, SMEM_BYTES>>>(data, bias, chunk_idx, out,
                                              D, H, T, sample);
}